// round 7
// baseline (speedup 1.0000x reference)
#include <cuda_runtime.h>
#include <cuda_bf16.h>
#include <math.h>
#include <stdint.h>

#define DDIM 256
#define PDIM 64
#define MTILE 64
#define NTHREADS 256

// pitches (bytes), ≡16 mod 128 -> conflict-free ldmatrix row sets
#define QP 272    // Q splits [64 m][128 k] bf16 + pad (per K-half)
#define CP 272    // C splits [64 p][128 k] bf16 + pad (per K-half)
#define SP 272    // sims [64 m][64 p] f32 + pad
#define WP 144    // W splits [64 m][64 p] bf16 + pad

// ---- smem byte offsets ----
#define CH_O 0            // C hi (per k-half; reused as C[d-half] for GEMM2)
#define CM_O 17408
#define CL_O 34816
#define QH_O 52224        // Q hi (per k-half)
#define QM_O 69632
#define QL_O 87040
#define S0_O 52224        // sims partials (alias QH/QM, dead after GEMM1)
#define S1_O 69632
#define WH_O 52224        // W splits (alias sims, dead after softmax+sync)
#define WL_O 61440
#define QSS_O 104448      // 64 f32
#define CQQ_O 104704      // 64 f32
#define CISM_O 104960     // 64 f32
#define NEGM_O 105216     // 64 f32
#define SMEM_BYTES 105472

__device__ __forceinline__ uint32_t smem_u32(const void* p) {
    uint32_t a;
    asm("{ .reg .u64 t; cvta.to.shared.u64 t, %1; cvt.u32.u64 %0, t; }" : "=r"(a) : "l"(p));
    return a;
}
__device__ __forceinline__ void ldsm4(uint32_t addr, uint32_t& r0, uint32_t& r1,
                                      uint32_t& r2, uint32_t& r3) {
    asm volatile("ldmatrix.sync.aligned.m8n8.x4.shared.b16 {%0,%1,%2,%3}, [%4];"
                 : "=r"(r0), "=r"(r1), "=r"(r2), "=r"(r3) : "r"(addr));
}
__device__ __forceinline__ void ldsm4t(uint32_t addr, uint32_t& r0, uint32_t& r1,
                                       uint32_t& r2, uint32_t& r3) {
    asm volatile("ldmatrix.sync.aligned.m8n8.x4.trans.shared.b16 {%0,%1,%2,%3}, [%4];"
                 : "=r"(r0), "=r"(r1), "=r"(r2), "=r"(r3) : "r"(addr));
}
__device__ __forceinline__ void mma16816(float* d, uint32_t a0, uint32_t a1, uint32_t a2,
                                         uint32_t a3, uint32_t b0, uint32_t b1) {
    asm volatile("mma.sync.aligned.m16n8k16.row.col.f32.bf16.bf16.f32 "
                 "{%0,%1,%2,%3}, {%4,%5,%6,%7}, {%8,%9}, {%0,%1,%2,%3};"
                 : "+f"(d[0]), "+f"(d[1]), "+f"(d[2]), "+f"(d[3])
                 : "r"(a0), "r"(a1), "r"(a2), "r"(a3), "r"(b0), "r"(b1));
}

__device__ __forceinline__ void split3(float x, unsigned short& h, unsigned short& m,
                                       unsigned short& l) {
    __nv_bfloat16 bh = __float2bfloat16(x);
    float r = x - __bfloat162float(bh);
    __nv_bfloat16 bm = __float2bfloat16(r);
    __nv_bfloat16 bl = __float2bfloat16(r - __bfloat162float(bm));
    h = __bfloat16_as_ushort(bh);
    m = __bfloat16_as_ushort(bm);
    l = __bfloat16_as_ushort(bl);
}
__device__ __forceinline__ void split2(float x, unsigned short& h, unsigned short& l) {
    __nv_bfloat16 bh = __float2bfloat16(x);
    __nv_bfloat16 bl = __float2bfloat16(x - __bfloat162float(bh));
    h = __bfloat16_as_ushort(bh);
    l = __bfloat16_as_ushort(bl);
}
__device__ __forceinline__ uint32_t pk(unsigned short a, unsigned short b) {
    return (uint32_t)a | ((uint32_t)b << 16);
}
__device__ __forceinline__ void conv8(const float4* src, char* dh, char* dm, char* dl,
                                      uint32_t off, float& acc) {
    float4 a = src[0], b = src[1];
    float xs[8] = {a.x, a.y, a.z, a.w, b.x, b.y, b.z, b.w};
    unsigned short h[8], m[8], l[8];
    #pragma unroll
    for (int i = 0; i < 8; ++i) {
        acc = fmaf(xs[i], xs[i], acc);
        split3(xs[i], h[i], m[i], l[i]);
    }
    *(uint4*)(dh + off) = make_uint4(pk(h[0], h[1]), pk(h[2], h[3]), pk(h[4], h[5]), pk(h[6], h[7]));
    *(uint4*)(dm + off) = make_uint4(pk(m[0], m[1]), pk(m[2], m[3]), pk(m[4], m[5]), pk(m[6], m[7]));
    *(uint4*)(dl + off) = make_uint4(pk(l[0], l[1]), pk(l[2], l[3]), pk(l[4], l[5]), pk(l[6], l[7]));
}
__device__ __forceinline__ void conv8_2(const float4* src, char* dh, char* dl, uint32_t off) {
    float4 a = src[0], b = src[1];
    float xs[8] = {a.x, a.y, a.z, a.w, b.x, b.y, b.z, b.w};
    unsigned short h[8], l[8];
    #pragma unroll
    for (int i = 0; i < 8; ++i) split2(xs[i], h[i], l[i]);
    *(uint4*)(dh + off) = make_uint4(pk(h[0], h[1]), pk(h[2], h[3]), pk(h[4], h[5]), pk(h[6], h[7]));
    *(uint4*)(dl + off) = make_uint4(pk(l[0], l[1]), pk(l[2], l[3]), pk(l[4], l[5]), pk(l[6], l[7]));
}

// GEMM1: warp computes 32x32 (m x p) tile over the current 128-k half, 3 split passes
__device__ __forceinline__ void gemm1_half(uint32_t smb, int g, int mrow, int ncol,
                                           int lane, float acc[8][4]) {
    const uint32_t qofs[6] = {QH_O, QH_O, QM_O, QH_O, QL_O, QM_O};
    const uint32_t cofs[6] = {CH_O, CM_O, CH_O, CL_O, CH_O, CM_O};
    const uint32_t lrow = (uint32_t)(lane & 15);
    const uint32_t lk = (uint32_t)((lane >> 4) * 16);
    #pragma unroll 1
    for (int ps = 0; ps < 3; ++ps) {
        uint32_t ab = smb + qofs[g * 3 + ps] + (mrow + lrow) * QP + lk;
        uint32_t bb = smb + cofs[g * 3 + ps] + (ncol + lrow) * CP + lk;
        uint32_t bb2 = bb + 16 * CP;
        #pragma unroll
        for (int ks = 0; ks < 8; ++ks) {
            uint32_t a0, a1, a2, a3, a4, a5, a6, a7, e0, e1, e2, e3, f0, f1, f2, f3;
            ldsm4(ab + ks * 32, a0, a1, a2, a3);
            ldsm4(ab + 16 * QP + ks * 32, a4, a5, a6, a7);
            ldsm4(bb + ks * 32, e0, e1, e2, e3);
            ldsm4(bb2 + ks * 32, f0, f1, f2, f3);
            mma16816(acc[0], a0, a1, a2, a3, e0, e2);
            mma16816(acc[1], a0, a1, a2, a3, e1, e3);
            mma16816(acc[2], a0, a1, a2, a3, f0, f2);
            mma16816(acc[3], a0, a1, a2, a3, f1, f3);
            mma16816(acc[4], a4, a5, a6, a7, e0, e2);
            mma16816(acc[5], a4, a5, a6, a7, e1, e3);
            mma16816(acc[6], a4, a5, a6, a7, f0, f2);
            mma16816(acc[7], a4, a5, a6, a7, f1, f3);
        }
    }
}

// GEMM2: ctx[m][dglob + 0..127] = sum_p W[m][p] * Cbuf[p][d]; warp = 32x32 tile
__device__ __forceinline__ void gemm2_half(uint32_t smb, int mrow2, int dtile, int lane,
                                           float* gctx, int mbase, int dglob) {
    float dd[8][4];
    #pragma unroll
    for (int i = 0; i < 8; ++i)
        #pragma unroll
        for (int j = 0; j < 4; ++j) dd[i][j] = 0.f;

    const uint32_t wofs[3] = {WH_O, WH_O, WL_O};
    const uint32_t cofs2[3] = {CH_O, CM_O, CH_O};   // C mid == split2-lo of C
    const uint32_t lrow = (uint32_t)(lane & 15);
    const uint32_t lk = (uint32_t)((lane >> 4) * 16);
    const uint32_t btrow = (uint32_t)((lane >> 4) * 8 + (lane & 7));
    const uint32_t btcol = (uint32_t)(((lane >> 3) & 1) * 16);

    #pragma unroll 1
    for (int ps = 0; ps < 3; ++ps) {
        uint32_t ab = smb + wofs[ps] + (mrow2 + lrow) * WP + lk;
        uint32_t bb = smb + cofs2[ps] + btrow * CP + dtile * 2 + btcol;
        #pragma unroll
        for (int ks = 0; ks < 4; ++ks) {
            uint32_t a0, a1, a2, a3, a4, a5, a6, a7;
            ldsm4(ab + ks * 32, a0, a1, a2, a3);
            ldsm4(ab + 16 * WP + ks * 32, a4, a5, a6, a7);
            #pragma unroll
            for (int nt = 0; nt < 2; ++nt) {
                uint32_t r0, r1, r2, r3;
                ldsm4t(bb + ks * 16 * CP + nt * 32, r0, r1, r2, r3);
                mma16816(dd[nt * 2 + 0], a0, a1, a2, a3, r0, r2);
                mma16816(dd[nt * 2 + 1], a0, a1, a2, a3, r1, r3);
                mma16816(dd[4 + nt * 2 + 0], a4, a5, a6, a7, r0, r2);
                mma16816(dd[4 + nt * 2 + 1], a4, a5, a6, a7, r1, r3);
            }
        }
    }
    const int r0l = lane >> 2;
    const int cb = (lane & 3) * 2;
    #pragma unroll
    for (int mf = 0; mf < 2; ++mf) {
        float* gr0 = gctx + (size_t)(mbase + mrow2 + mf * 16 + r0l) * DDIM;
        float* gr1 = gr0 + 8 * DDIM;
        #pragma unroll
        for (int nt = 0; nt < 2; ++nt)
            #pragma unroll
            for (int n8 = 0; n8 < 2; ++n8) {
                float* a = dd[mf * 4 + nt * 2 + n8];
                int col = dglob + dtile + nt * 16 + n8 * 8 + cb;
                *(float2*)(gr0 + col) = make_float2(a[0], a[1]);
                *(float2*)(gr1 + col) = make_float2(a[2], a[3]);
            }
    }
}

__global__ void __launch_bounds__(NTHREADS, 2)
centroid_hmma3_kernel(const float* __restrict__ gq,
                      const float* __restrict__ gc,
                      const int* __restrict__ gmask,
                      float* __restrict__ gctx,
                      float* __restrict__ gw,
                      float* __restrict__ ghard)
{
    extern __shared__ char sm[];
    const uint32_t smb = smem_u32(sm);
    const int t = threadIdx.x;
    const int wid = t >> 5, lane = t & 31;
    const int mbase = blockIdx.x * MTILE;

    float* qssf = (float*)(sm + QSS_O);
    float* cqqf = (float*)(sm + CQQ_O);
    float* cism = (float*)(sm + CISM_O);
    float* negm = (float*)(sm + NEGM_O);

    // GEMM1 mapping: group g (3 of 6 split passes), 2M x 2N grid of 32x32 tiles
    const int g = wid >> 2;
    const int mrow = ((wid >> 1) & 1) * 32;
    const int ncol = (wid & 1) * 32;

    const int row4 = t >> 2, seg4 = t & 3;   // conversions: 4 thr/row, 32 elems each
    float cacc = 0.f, qacc = 0.f;

    float acc[8][4];
    #pragma unroll
    for (int i = 0; i < 8; ++i)
        #pragma unroll
        for (int j = 0; j < 4; ++j) acc[i][j] = 0.f;

    // ================= GEMM1 over two K-halves =================
    #pragma unroll 1
    for (int kc = 0; kc < 2; ++kc) {
        // convert C k-half [64][128]
        {
            const float4* src = (const float4*)(gc + (size_t)row4 * DDIM + kc * 128 + seg4 * 32);
            uint32_t base = (uint32_t)(row4 * CP + seg4 * 64);
            #pragma unroll
            for (int j = 0; j < 4; ++j)
                conv8(src + 2 * j, sm + CH_O, sm + CM_O, sm + CL_O, base + j * 16, cacc);
        }
        // convert Q k-half [64][128]
        {
            const float4* src = (const float4*)(gq + (size_t)(mbase + row4) * DDIM + kc * 128 + seg4 * 32);
            uint32_t base = (uint32_t)(row4 * QP + seg4 * 64);
            #pragma unroll
            for (int j = 0; j < 4; ++j)
                conv8(src + 2 * j, sm + QH_O, sm + QM_O, sm + QL_O, base + j * 16, qacc);
        }
        if (kc == 1) {
            cacc += __shfl_xor_sync(0xffffffffu, cacc, 1);
            cacc += __shfl_xor_sync(0xffffffffu, cacc, 2);
            qacc += __shfl_xor_sync(0xffffffffu, qacc, 1);
            qacc += __shfl_xor_sync(0xffffffffu, qacc, 2);
            if (seg4 == 0) {
                cqqf[row4] = cacc;
                qssf[row4] = qacc;
            }
        }
        __syncthreads();
        gemm1_half(smb, g, mrow, ncol, lane, acc);
        __syncthreads();   // operand buffers reusable
    }

    // ---- store partial sims + masks/norms ----
    {
        char* sbase = sm + (g ? S1_O : S0_O);
        const int r0 = mrow + (lane >> 2);
        const int cb = ncol + (lane & 3) * 2;
        #pragma unroll
        for (int mf = 0; mf < 2; ++mf)
            #pragma unroll
            for (int nf = 0; nf < 4; ++nf) {
                float* a = acc[mf * 4 + nf];
                *(float2*)(sbase + (r0 + mf * 16) * SP + (cb + nf * 8) * 4) = make_float2(a[0], a[1]);
                *(float2*)(sbase + (r0 + mf * 16 + 8) * SP + (cb + nf * 8) * 4) = make_float2(a[2], a[3]);
            }
    }
    if (t < 64) {
        int mk = gmask[t];
        cism[t] = mk ? rsqrtf(fmaxf(cqqf[t], 1e-24f)) : 0.f;
        negm[t] = mk ? 0.f : -1e9f;
    }
    __syncthreads();

    // ================= softmax + argmax: 4 threads per row =================
    {
        const int m = t >> 2, part = t & 3;
        const float qr = rsqrtf(fmaxf(qssf[m], 1e-24f));
        const float4* s0 = (const float4*)(sm + S0_O + m * SP) + part * 4;
        const float4* s1 = (const float4*)(sm + S1_O + m * SP) + part * 4;
        float s[16];
        float mx = -INFINITY;
        int mi = PDIM;
        #pragma unroll
        for (int gg = 0; gg < 4; ++gg) {
            float4 v = s0[gg], u = s1[gg];
            float vv[4] = {v.x + u.x, v.y + u.y, v.z + u.z, v.w + u.w};
            #pragma unroll
            for (int i = 0; i < 4; ++i) {
                int p = part * 16 + gg * 4 + i;
                float val = fmaf(vv[i] * qr, cism[p], negm[p]);
                s[gg * 4 + i] = val;
                if (val > mx) { mx = val; mi = p; }     // strict >: first index wins
            }
        }
        #pragma unroll
        for (int off = 1; off < 4; off <<= 1) {
            float omx = __shfl_xor_sync(0xffffffffu, mx, off);
            int   omi = __shfl_xor_sync(0xffffffffu, mi, off);
            if (omx > mx || (omx == mx && omi < mi)) { mx = omx; mi = omi; }
        }
        float ssum = 0.f;
        #pragma unroll
        for (int i = 0; i < 16; ++i) {
            float e = expf(s[i] - mx);
            s[i] = e;
            ssum += e;
        }
        #pragma unroll
        for (int off = 1; off < 4; off <<= 1)
            ssum += __shfl_xor_sync(0xffffffffu, ssum, off);
        const float inv = 1.0f / ssum;

        // weights + splits into registers
        uint4 whp[2], wlp[2];
        float4 gwo[4];
        #pragma unroll
        for (int gg = 0; gg < 4; ++gg) {
            float w0 = s[4 * gg + 0] * inv, w1 = s[4 * gg + 1] * inv;
            float w2 = s[4 * gg + 2] * inv, w3 = s[4 * gg + 3] * inv;
            gwo[gg] = make_float4(w0, w1, w2, w3);
            unsigned short h0, l0, h1, l1, h2, l2, h3, l3;
            split2(w0, h0, l0); split2(w1, h1, l1);
            split2(w2, h2, l2); split2(w3, h3, l3);
            ((uint2*)whp)[gg] = make_uint2(pk(h0, h1), pk(h2, h3));
            ((uint2*)wlp)[gg] = make_uint2(pk(l0, l1), pk(l2, l3));
        }
        __syncthreads();   // all sims reads done before W overwrites the alias
        float4* gwp = (float4*)(gw + (size_t)(mbase + m) * PDIM + part * 16);
        #pragma unroll
        for (int gg = 0; gg < 4; ++gg) gwp[gg] = gwo[gg];
        *(uint4*)(sm + WH_O + m * WP + part * 32) = whp[0];
        *(uint4*)(sm + WH_O + m * WP + part * 32 + 16) = whp[1];
        *(uint4*)(sm + WL_O + m * WP + part * 32) = wlp[0];
        *(uint4*)(sm + WL_O + m * WP + part * 32 + 16) = wlp[1];
        if (part == 0) ghard[mbase + m] = (float)mi;
    }
    __syncthreads();

    // ================= GEMM2 =================
    const int mrow2 = (wid & 1) * 32;
    const int dtile = (wid >> 1) * 32;
    // d-half 1 first: C buffer currently holds k/d = 128..255
    gemm2_half(smb, mrow2, dtile, lane, gctx, mbase, 128);
    __syncthreads();
    // reconvert C d = 0..127 (hi+mid splits only)
    {
        const float4* src = (const float4*)(gc + (size_t)row4 * DDIM + seg4 * 32);
        uint32_t base = (uint32_t)(row4 * CP + seg4 * 64);
        #pragma unroll
        for (int j = 0; j < 4; ++j)
            conv8_2(src + 2 * j, sm + CH_O, sm + CM_O, base + j * 16);
    }
    __syncthreads();
    gemm2_half(smb, mrow2, dtile, lane, gctx, mbase, 0);
}

extern "C" void kernel_launch(void* const* d_in, const int* in_sizes, int n_in,
                              void* d_out, int out_size)
{
    const float* q = (const float*)d_in[0];
    const float* c = (const float*)d_in[1];
    const int*   mask = (const int*)d_in[2];

    const int Pn = in_sizes[2];              // 64
    const int Dn = in_sizes[1] / Pn;         // 256
    const int B  = in_sizes[0] / Dn;         // 131072

    float* out  = (float*)d_out;
    float* ctx  = out;                           // [B, D]
    float* w    = out + (size_t)B * Dn;          // [B, P]
    float* hard = w + (size_t)B * Pn;            // [B]

    cudaFuncSetAttribute(centroid_hmma3_kernel,
                         cudaFuncAttributeMaxDynamicSharedMemorySize, SMEM_BYTES);
    centroid_hmma3_kernel<<<B / MTILE, NTHREADS, SMEM_BYTES>>>(q, c, mask, ctx, w, hard);
}

// round 8
// speedup vs baseline: 1.0622x; 1.0622x over previous
#include <cuda_runtime.h>
#include <cuda_bf16.h>
#include <math.h>
#include <stdint.h>

#define DDIM 256
#define PDIM 64
#define MTILE 64
#define NTHREADS 256

// pitches (bytes), ≡16 mod 128 -> conflict-free ldmatrix row sets
#define QP 272    // Q splits [64 m][128 k] bf16 + pad (per K-half)
#define CP 272    // C splits [64 p][128 k] bf16 + pad (per K-half)
#define SP 272    // sims [64 m][64 p] f32 + pad
#define WP 144    // W splits [64 m][64 p] bf16 + pad

// ---- smem byte offsets ----
#define CH_O 0            // C hi (per k-half; reused as C d-half for GEMM2)
#define CM_O 17408
#define CL_O 34816
#define QH_O 52224        // Q hi (per k-half)
#define QM_O 69632
#define QL_O 87040
#define S0_O 52224        // sims partials (alias QH/QM, dead after GEMM1)
#define S1_O 69632
#define WH_O 52224        // W splits (alias sims, written after softmax reads)
#define WL_O 61440
#define QSS_O 104448      // 64 f32
#define CISM_O 104704     // 64 f32
#define NEGM_O 104960     // 64 f32
#define SMEM_BYTES 105216

// ---- precomputed centroid splits (written by prep kernel, read by main) ----
__device__ __align__(16) unsigned short gCH[PDIM * DDIM];
__device__ __align__(16) unsigned short gCM[PDIM * DDIM];
__device__ __align__(16) unsigned short gCL[PDIM * DDIM];
__device__ float gCISM[PDIM];
__device__ float gNEGM[PDIM];

__device__ __forceinline__ uint32_t smem_u32(const void* p) {
    uint32_t a;
    asm("{ .reg .u64 t; cvta.to.shared.u64 t, %1; cvt.u32.u64 %0, t; }" : "=r"(a) : "l"(p));
    return a;
}
#define CPA16(dst, src) \
    asm volatile("cp.async.cg.shared.global [%0], [%1], 16;" :: "r"(dst), "l"(src) : "memory")
#define CPA_COMMIT() asm volatile("cp.async.commit_group;" ::: "memory")
#define CPA_WAIT0()  asm volatile("cp.async.wait_group 0;" ::: "memory")

__device__ __forceinline__ void ldsm4(uint32_t addr, uint32_t& r0, uint32_t& r1,
                                      uint32_t& r2, uint32_t& r3) {
    asm volatile("ldmatrix.sync.aligned.m8n8.x4.shared.b16 {%0,%1,%2,%3}, [%4];"
                 : "=r"(r0), "=r"(r1), "=r"(r2), "=r"(r3) : "r"(addr));
}
__device__ __forceinline__ void ldsm4t(uint32_t addr, uint32_t& r0, uint32_t& r1,
                                       uint32_t& r2, uint32_t& r3) {
    asm volatile("ldmatrix.sync.aligned.m8n8.x4.trans.shared.b16 {%0,%1,%2,%3}, [%4];"
                 : "=r"(r0), "=r"(r1), "=r"(r2), "=r"(r3) : "r"(addr));
}
__device__ __forceinline__ void mma16816(float* d, uint32_t a0, uint32_t a1, uint32_t a2,
                                         uint32_t a3, uint32_t b0, uint32_t b1) {
    asm volatile("mma.sync.aligned.m16n8k16.row.col.f32.bf16.bf16.f32 "
                 "{%0,%1,%2,%3}, {%4,%5,%6,%7}, {%8,%9}, {%0,%1,%2,%3};"
                 : "+f"(d[0]), "+f"(d[1]), "+f"(d[2]), "+f"(d[3])
                 : "r"(a0), "r"(a1), "r"(a2), "r"(a3), "r"(b0), "r"(b1));
}

__device__ __forceinline__ void split3(float x, unsigned short& h, unsigned short& m,
                                       unsigned short& l) {
    __nv_bfloat16 bh = __float2bfloat16(x);
    float r = x - __bfloat162float(bh);
    __nv_bfloat16 bm = __float2bfloat16(r);
    __nv_bfloat16 bl = __float2bfloat16(r - __bfloat162float(bm));
    h = __bfloat16_as_ushort(bh);
    m = __bfloat16_as_ushort(bm);
    l = __bfloat16_as_ushort(bl);
}
__device__ __forceinline__ void split2(float x, unsigned short& h, unsigned short& l) {
    __nv_bfloat16 bh = __float2bfloat16(x);
    __nv_bfloat16 bl = __float2bfloat16(x - __bfloat162float(bh));
    h = __bfloat16_as_ushort(bh);
    l = __bfloat16_as_ushort(bl);
}
__device__ __forceinline__ uint32_t pk(unsigned short a, unsigned short b) {
    return (uint32_t)a | ((uint32_t)b << 16);
}
__device__ __forceinline__ void conv8(const float4* src, char* dh, char* dm, char* dl,
                                      uint32_t off, float& acc) {
    float4 a = src[0], b = src[1];
    float xs[8] = {a.x, a.y, a.z, a.w, b.x, b.y, b.z, b.w};
    unsigned short h[8], m[8], l[8];
    #pragma unroll
    for (int i = 0; i < 8; ++i) {
        acc = fmaf(xs[i], xs[i], acc);
        split3(xs[i], h[i], m[i], l[i]);
    }
    *(uint4*)(dh + off) = make_uint4(pk(h[0], h[1]), pk(h[2], h[3]), pk(h[4], h[5]), pk(h[6], h[7]));
    *(uint4*)(dm + off) = make_uint4(pk(m[0], m[1]), pk(m[2], m[3]), pk(m[4], m[5]), pk(m[6], m[7]));
    *(uint4*)(dl + off) = make_uint4(pk(l[0], l[1]), pk(l[2], l[3]), pk(l[4], l[5]), pk(l[6], l[7]));
}

// ================= prep kernel: split C once, norms + mask =================
__global__ void centroid_prep(const float* __restrict__ gc, const int* __restrict__ gmask) {
    const int t = threadIdx.x;           // 256
    const int row = t >> 2, seg = t & 3; // 4 thr/row, 64 elems each
    float acc = 0.f;
    #pragma unroll
    for (int j = 0; j < 8; ++j) {
        const float4* src = (const float4*)(gc + (size_t)row * DDIM + seg * 64 + j * 8);
        float4 a = src[0], b = src[1];
        float xs[8] = {a.x, a.y, a.z, a.w, b.x, b.y, b.z, b.w};
        unsigned short h[8], m[8], l[8];
        #pragma unroll
        for (int i = 0; i < 8; ++i) {
            acc = fmaf(xs[i], xs[i], acc);
            split3(xs[i], h[i], m[i], l[i]);
        }
        const int idx = row * DDIM + seg * 64 + j * 8;
        *(uint4*)(gCH + idx) = make_uint4(pk(h[0], h[1]), pk(h[2], h[3]), pk(h[4], h[5]), pk(h[6], h[7]));
        *(uint4*)(gCM + idx) = make_uint4(pk(m[0], m[1]), pk(m[2], m[3]), pk(m[4], m[5]), pk(m[6], m[7]));
        *(uint4*)(gCL + idx) = make_uint4(pk(l[0], l[1]), pk(l[2], l[3]), pk(l[4], l[5]), pk(l[6], l[7]));
    }
    acc += __shfl_xor_sync(0xffffffffu, acc, 1);
    acc += __shfl_xor_sync(0xffffffffu, acc, 2);
    if (seg == 0) {
        int mk = gmask[row];
        gCISM[row] = mk ? rsqrtf(fmaxf(acc, 1e-24f)) : 0.f;
        gNEGM[row] = mk ? 0.f : -1e9f;
    }
}

// copy one k-half slice (256B/row) of a C split into pitched smem via cp.async
__device__ __forceinline__ void copy_chalf(uint32_t dstbase, const unsigned short* gsrc,
                                           int row, int seg, int kc) {
    uint32_t dst = dstbase + (uint32_t)(row * CP + seg * 64);
    uint64_t src = __cvta_generic_to_global(gsrc + row * DDIM + kc * 128 + seg * 32);
    #pragma unroll
    for (int j = 0; j < 4; ++j) CPA16(dst + j * 16, src + j * 16);
}

// GEMM1: warp computes 32x32 (m x p) tile over the current 128-k half, 3 split passes
__device__ __forceinline__ void gemm1_half(uint32_t smb, int g, int mrow, int ncol,
                                           int lane, float acc[8][4]) {
    const uint32_t qofs[6] = {QH_O, QH_O, QM_O, QH_O, QL_O, QM_O};
    const uint32_t cofs[6] = {CH_O, CM_O, CH_O, CL_O, CH_O, CM_O};
    const uint32_t lrow = (uint32_t)(lane & 15);
    const uint32_t lk = (uint32_t)((lane >> 4) * 16);
    #pragma unroll 1
    for (int ps = 0; ps < 3; ++ps) {
        uint32_t ab = smb + qofs[g * 3 + ps] + (mrow + lrow) * QP + lk;
        uint32_t bb = smb + cofs[g * 3 + ps] + (ncol + lrow) * CP + lk;
        uint32_t bb2 = bb + 16 * CP;
        #pragma unroll
        for (int ks = 0; ks < 8; ++ks) {
            uint32_t a0, a1, a2, a3, a4, a5, a6, a7, e0, e1, e2, e3, f0, f1, f2, f3;
            ldsm4(ab + ks * 32, a0, a1, a2, a3);
            ldsm4(ab + 16 * QP + ks * 32, a4, a5, a6, a7);
            ldsm4(bb + ks * 32, e0, e1, e2, e3);
            ldsm4(bb2 + ks * 32, f0, f1, f2, f3);
            mma16816(acc[0], a0, a1, a2, a3, e0, e2);
            mma16816(acc[1], a0, a1, a2, a3, e1, e3);
            mma16816(acc[2], a0, a1, a2, a3, f0, f2);
            mma16816(acc[3], a0, a1, a2, a3, f1, f3);
            mma16816(acc[4], a4, a5, a6, a7, e0, e2);
            mma16816(acc[5], a4, a5, a6, a7, e1, e3);
            mma16816(acc[6], a4, a5, a6, a7, f0, f2);
            mma16816(acc[7], a4, a5, a6, a7, f1, f3);
        }
    }
}

// GEMM2: ctx[m][dglob + dtile..] = sum_p W[m][p] * Cbuf[p][d]; warp = 32x32 tile
__device__ __forceinline__ void gemm2_half(uint32_t smb, int mrow2, int dtile, int lane,
                                           float* gctx, int mbase, int dglob) {
    float dd[8][4];
    #pragma unroll
    for (int i = 0; i < 8; ++i)
        #pragma unroll
        for (int j = 0; j < 4; ++j) dd[i][j] = 0.f;

    const uint32_t wofs[3] = {WH_O, WH_O, WL_O};
    const uint32_t cofs2[3] = {CH_O, CM_O, CH_O};   // C mid == split2-lo of C
    const uint32_t lrow = (uint32_t)(lane & 15);
    const uint32_t lk = (uint32_t)((lane >> 4) * 16);
    const uint32_t btrow = (uint32_t)((lane >> 4) * 8 + (lane & 7));
    const uint32_t btcol = (uint32_t)(((lane >> 3) & 1) * 16);

    #pragma unroll 1
    for (int ps = 0; ps < 3; ++ps) {
        uint32_t ab = smb + wofs[ps] + (mrow2 + lrow) * WP + lk;
        uint32_t bb = smb + cofs2[ps] + btrow * CP + dtile * 2 + btcol;
        #pragma unroll
        for (int ks = 0; ks < 4; ++ks) {
            uint32_t a0, a1, a2, a3, a4, a5, a6, a7;
            ldsm4(ab + ks * 32, a0, a1, a2, a3);
            ldsm4(ab + 16 * WP + ks * 32, a4, a5, a6, a7);
            #pragma unroll
            for (int nt = 0; nt < 2; ++nt) {
                uint32_t r0, r1, r2, r3;
                ldsm4t(bb + ks * 16 * CP + nt * 32, r0, r1, r2, r3);
                mma16816(dd[nt * 2 + 0], a0, a1, a2, a3, r0, r2);
                mma16816(dd[nt * 2 + 1], a0, a1, a2, a3, r1, r3);
                mma16816(dd[4 + nt * 2 + 0], a4, a5, a6, a7, r0, r2);
                mma16816(dd[4 + nt * 2 + 1], a4, a5, a6, a7, r1, r3);
            }
        }
    }
    const int r0l = lane >> 2;
    const int cb = (lane & 3) * 2;
    #pragma unroll
    for (int mf = 0; mf < 2; ++mf) {
        float* gr0 = gctx + (size_t)(mbase + mrow2 + mf * 16 + r0l) * DDIM;
        float* gr1 = gr0 + 8 * DDIM;
        #pragma unroll
        for (int nt = 0; nt < 2; ++nt)
            #pragma unroll
            for (int n8 = 0; n8 < 2; ++n8) {
                float* a = dd[mf * 4 + nt * 2 + n8];
                int col = dglob + dtile + nt * 16 + n8 * 8 + cb;
                *(float2*)(gr0 + col) = make_float2(a[0], a[1]);
                *(float2*)(gr1 + col) = make_float2(a[2], a[3]);
            }
    }
}

__global__ void __launch_bounds__(NTHREADS, 2)
centroid_main(const float* __restrict__ gq,
              float* __restrict__ gctx,
              float* __restrict__ gw,
              float* __restrict__ ghard)
{
    extern __shared__ char sm[];
    const uint32_t smb = smem_u32(sm);
    const int t = threadIdx.x;
    const int wid = t >> 5, lane = t & 31;
    const int mbase = blockIdx.x * MTILE;

    float* qssf = (float*)(sm + QSS_O);
    float* cism = (float*)(sm + CISM_O);
    float* negm = (float*)(sm + NEGM_O);

    const int g = wid >> 2;
    const int mrow = ((wid >> 1) & 1) * 32;
    const int ncol = (wid & 1) * 32;
    const int row4 = t >> 2, seg4 = t & 3;

    if (t < 64) {
        cism[t] = gCISM[t];
        negm[t] = gNEGM[t];
    }

    float qacc = 0.f;
    float acc[8][4];
    #pragma unroll
    for (int i = 0; i < 8; ++i)
        #pragma unroll
        for (int j = 0; j < 4; ++j) acc[i][j] = 0.f;

    // ================= GEMM1 over two K-halves =================
    #pragma unroll 1
    for (int kc = 0; kc < 2; ++kc) {
        // async-copy precomputed C splits (k-half)
        copy_chalf(smb + CH_O, gCH, row4, seg4, kc);
        copy_chalf(smb + CM_O, gCM, row4, seg4, kc);
        copy_chalf(smb + CL_O, gCL, row4, seg4, kc);
        CPA_COMMIT();
        // convert Q k-half [64][128] (overlaps with cp.async)
        {
            const float4* src = (const float4*)(gq + (size_t)(mbase + row4) * DDIM + kc * 128 + seg4 * 32);
            uint32_t base = (uint32_t)(row4 * QP + seg4 * 64);
            #pragma unroll
            for (int j = 0; j < 4; ++j)
                conv8(src + 2 * j, sm + QH_O, sm + QM_O, sm + QL_O, base + j * 16, qacc);
        }
        if (kc == 1) {
            qacc += __shfl_xor_sync(0xffffffffu, qacc, 1);
            qacc += __shfl_xor_sync(0xffffffffu, qacc, 2);
            if (seg4 == 0) qssf[row4] = qacc;
        }
        CPA_WAIT0();
        __syncthreads();
        gemm1_half(smb, g, mrow, ncol, lane, acc);
        __syncthreads();
    }

    // ---- store partial sims ----
    {
        char* sbase = sm + (g ? S1_O : S0_O);
        const int r0 = mrow + (lane >> 2);
        const int cb = ncol + (lane & 3) * 2;
        #pragma unroll
        for (int mf = 0; mf < 2; ++mf)
            #pragma unroll
            for (int nf = 0; nf < 4; ++nf) {
                float* a = acc[mf * 4 + nf];
                *(float2*)(sbase + (r0 + mf * 16) * SP + (cb + nf * 8) * 4) = make_float2(a[0], a[1]);
                *(float2*)(sbase + (r0 + mf * 16 + 8) * SP + (cb + nf * 8) * 4) = make_float2(a[2], a[3]);
            }
    }
    __syncthreads();

    // ================= softmax + argmax: 4 threads per row =================
    {
        const int m = t >> 2, part = t & 3;
        const float qr = rsqrtf(fmaxf(qssf[m], 1e-24f));
        const float4* s0 = (const float4*)(sm + S0_O + m * SP) + part * 4;
        const float4* s1 = (const float4*)(sm + S1_O + m * SP) + part * 4;
        float s[16];
        float mx = -INFINITY;
        int mi = PDIM;
        #pragma unroll
        for (int gg = 0; gg < 4; ++gg) {
            float4 v = s0[gg], u = s1[gg];
            float vv[4] = {v.x + u.x, v.y + u.y, v.z + u.z, v.w + u.w};
            #pragma unroll
            for (int i = 0; i < 4; ++i) {
                int p = part * 16 + gg * 4 + i;
                float val = fmaf(vv[i] * qr, cism[p], negm[p]);
                s[gg * 4 + i] = val;
                if (val > mx) { mx = val; mi = p; }     // strict >: first index wins
            }
        }
        #pragma unroll
        for (int off = 1; off < 4; off <<= 1) {
            float omx = __shfl_xor_sync(0xffffffffu, mx, off);
            int   omi = __shfl_xor_sync(0xffffffffu, mi, off);
            if (omx > mx || (omx == mx && omi < mi)) { mx = omx; mi = omi; }
        }
        float ssum = 0.f;
        #pragma unroll
        for (int i = 0; i < 16; ++i) {
            float e = expf(s[i] - mx);
            s[i] = e;
            ssum += e;
        }
        #pragma unroll
        for (int off = 1; off < 4; off <<= 1)
            ssum += __shfl_xor_sync(0xffffffffu, ssum, off);
        const float inv = 1.0f / ssum;

        uint4 whp[2], wlp[2];
        float4 gwo[4];
        #pragma unroll
        for (int gg = 0; gg < 4; ++gg) {
            float w0 = s[4 * gg + 0] * inv, w1 = s[4 * gg + 1] * inv;
            float w2 = s[4 * gg + 2] * inv, w3 = s[4 * gg + 3] * inv;
            gwo[gg] = make_float4(w0, w1, w2, w3);
            unsigned short h0, l0, h1, l1, h2, l2, h3, l3;
            split2(w0, h0, l0); split2(w1, h1, l1);
            split2(w2, h2, l2); split2(w3, h3, l3);
            ((uint2*)whp)[gg] = make_uint2(pk(h0, h1), pk(h2, h3));
            ((uint2*)wlp)[gg] = make_uint2(pk(l0, l1), pk(l2, l3));
        }
        __syncthreads();   // all sims reads done before W overwrites the alias
        float4* gwp = (float4*)(gw + (size_t)(mbase + m) * PDIM + part * 16);
        #pragma unroll
        for (int gg = 0; gg < 4; ++gg) gwp[gg] = gwo[gg];
        *(uint4*)(sm + WH_O + m * WP + part * 32) = whp[0];
        *(uint4*)(sm + WH_O + m * WP + part * 32 + 16) = whp[1];
        *(uint4*)(sm + WL_O + m * WP + part * 32) = wlp[0];
        *(uint4*)(sm + WL_O + m * WP + part * 32 + 16) = wlp[1];
        if (part == 0) ghard[mbase + m] = (float)mi;
    }
    __syncthreads();

    // ================= GEMM2 =================
    const int mrow2 = (wid & 1) * 32;
    const int dtile = (wid >> 1) * 32;
    // d-half 1 first: C buffers currently hold k/d = 128..255
    gemm2_half(smb, mrow2, dtile, lane, gctx, mbase, 128);
    __syncthreads();
    // async-copy C d-half 0 (hi + mid splits only)
    copy_chalf(smb + CH_O, gCH, row4, seg4, 0);
    copy_chalf(smb + CM_O, gCM, row4, seg4, 0);
    CPA_COMMIT();
    CPA_WAIT0();
    __syncthreads();
    gemm2_half(smb, mrow2, dtile, lane, gctx, mbase, 0);
}

extern "C" void kernel_launch(void* const* d_in, const int* in_sizes, int n_in,
                              void* d_out, int out_size)
{
    const float* q = (const float*)d_in[0];
    const float* c = (const float*)d_in[1];
    const int*   mask = (const int*)d_in[2];

    const int Pn = in_sizes[2];              // 64
    const int Dn = in_sizes[1] / Pn;         // 256
    const int B  = in_sizes[0] / Dn;         // 131072

    float* out  = (float*)d_out;
    float* ctx  = out;                           // [B, D]
    float* w    = out + (size_t)B * Dn;          // [B, P]
    float* hard = w + (size_t)B * Pn;            // [B]

    centroid_prep<<<1, 256>>>(c, mask);
    cudaFuncSetAttribute(centroid_main,
                         cudaFuncAttributeMaxDynamicSharedMemorySize, SMEM_BYTES);
    centroid_main<<<B / MTILE, NTHREADS, SMEM_BYTES>>>(q, ctx, w, hard);
}

// round 9
// speedup vs baseline: 1.2903x; 1.2148x over previous
#include <cuda_runtime.h>
#include <cuda_bf16.h>
#include <math.h>
#include <stdint.h>

#define DDIM 256
#define PDIM 64
#define MTILE 64
#define NTHREADS 256

// pitches (bytes), ≡16 mod 128 -> conflict-free ldmatrix row sets
#define KQP 144   // split buffers [64][64k] bf16 + 16B pad
#define SP  272   // sims [64 m][64 p] f32 + pad
#define WP  144   // W splits [64 m][64 p] bf16 + pad

// ---- smem offsets ----
#define QH_O 0
#define QM_O 9216
#define QL_O 18432
#define CH_O 27648
#define CM_O 36864
#define CL_O 46080
#define S0_O 0            // sims partials (alias Q/C, dead after GEMM1)
#define S1_O 17408
#define WH_O 34816        // W splits (above sims region)
#define WL_O 44032
#define C2H_O 0           // GEMM2 C d-quarter buffers (alias sims, dead)
#define C2M_O 9216
#define QSS_O 55296
#define CISM_O 55552
#define NEGM_O 55808
#define SMEM_BYTES 56064

// ---- precomputed centroid splits ----
__device__ __align__(16) unsigned short gCH[PDIM * DDIM];
__device__ __align__(16) unsigned short gCM[PDIM * DDIM];
__device__ __align__(16) unsigned short gCL[PDIM * DDIM];
__device__ float gCISM[PDIM];
__device__ float gNEGM[PDIM];

__device__ __forceinline__ uint32_t smem_u32(const void* p) {
    uint32_t a;
    asm("{ .reg .u64 t; cvta.to.shared.u64 t, %1; cvt.u32.u64 %0, t; }" : "=r"(a) : "l"(p));
    return a;
}
#define CPA16(dst, src) \
    asm volatile("cp.async.cg.shared.global [%0], [%1], 16;" :: "r"(dst), "l"(src) : "memory")
#define CPA_COMMIT() asm volatile("cp.async.commit_group;" ::: "memory")
#define CPA_WAIT0()  asm volatile("cp.async.wait_group 0;" ::: "memory")

__device__ __forceinline__ void ldsm4(uint32_t addr, uint32_t& r0, uint32_t& r1,
                                      uint32_t& r2, uint32_t& r3) {
    asm volatile("ldmatrix.sync.aligned.m8n8.x4.shared.b16 {%0,%1,%2,%3}, [%4];"
                 : "=r"(r0), "=r"(r1), "=r"(r2), "=r"(r3) : "r"(addr));
}
__device__ __forceinline__ void ldsm4t(uint32_t addr, uint32_t& r0, uint32_t& r1,
                                       uint32_t& r2, uint32_t& r3) {
    asm volatile("ldmatrix.sync.aligned.m8n8.x4.trans.shared.b16 {%0,%1,%2,%3}, [%4];"
                 : "=r"(r0), "=r"(r1), "=r"(r2), "=r"(r3) : "r"(addr));
}
__device__ __forceinline__ void mma16816(float* d, uint32_t a0, uint32_t a1, uint32_t a2,
                                         uint32_t a3, uint32_t b0, uint32_t b1) {
    asm volatile("mma.sync.aligned.m16n8k16.row.col.f32.bf16.bf16.f32 "
                 "{%0,%1,%2,%3}, {%4,%5,%6,%7}, {%8,%9}, {%0,%1,%2,%3};"
                 : "+f"(d[0]), "+f"(d[1]), "+f"(d[2]), "+f"(d[3])
                 : "r"(a0), "r"(a1), "r"(a2), "r"(a3), "r"(b0), "r"(b1));
}

__device__ __forceinline__ void split3(float x, unsigned short& h, unsigned short& m,
                                       unsigned short& l) {
    __nv_bfloat16 bh = __float2bfloat16(x);
    float r = x - __bfloat162float(bh);
    __nv_bfloat16 bm = __float2bfloat16(r);
    __nv_bfloat16 bl = __float2bfloat16(r - __bfloat162float(bm));
    h = __bfloat16_as_ushort(bh);
    m = __bfloat16_as_ushort(bm);
    l = __bfloat16_as_ushort(bl);
}
__device__ __forceinline__ void split2(float x, unsigned short& h, unsigned short& l) {
    __nv_bfloat16 bh = __float2bfloat16(x);
    __nv_bfloat16 bl = __float2bfloat16(x - __bfloat162float(bh));
    h = __bfloat16_as_ushort(bh);
    l = __bfloat16_as_ushort(bl);
}
__device__ __forceinline__ uint32_t pk(unsigned short a, unsigned short b) {
    return (uint32_t)a | ((uint32_t)b << 16);
}
__device__ __forceinline__ void conv8(const float4* src, char* dh, char* dm, char* dl,
                                      uint32_t off, float& acc) {
    float4 a = src[0], b = src[1];
    float xs[8] = {a.x, a.y, a.z, a.w, b.x, b.y, b.z, b.w};
    unsigned short h[8], m[8], l[8];
    #pragma unroll
    for (int i = 0; i < 8; ++i) {
        acc = fmaf(xs[i], xs[i], acc);
        split3(xs[i], h[i], m[i], l[i]);
    }
    *(uint4*)(dh + off) = make_uint4(pk(h[0], h[1]), pk(h[2], h[3]), pk(h[4], h[5]), pk(h[6], h[7]));
    *(uint4*)(dm + off) = make_uint4(pk(m[0], m[1]), pk(m[2], m[3]), pk(m[4], m[5]), pk(m[6], m[7]));
    *(uint4*)(dl + off) = make_uint4(pk(l[0], l[1]), pk(l[2], l[3]), pk(l[4], l[5]), pk(l[6], l[7]));
}

// ================= prep kernel =================
__global__ void centroid_prep(const float* __restrict__ gc, const int* __restrict__ gmask) {
    const int t = threadIdx.x;           // 256
    const int row = t >> 2, seg = t & 3;
    float acc = 0.f;
    #pragma unroll
    for (int j = 0; j < 8; ++j) {
        const float4* src = (const float4*)(gc + (size_t)row * DDIM + seg * 64 + j * 8);
        float4 a = src[0], b = src[1];
        float xs[8] = {a.x, a.y, a.z, a.w, b.x, b.y, b.z, b.w};
        unsigned short h[8], m[8], l[8];
        #pragma unroll
        for (int i = 0; i < 8; ++i) {
            acc = fmaf(xs[i], xs[i], acc);
            split3(xs[i], h[i], m[i], l[i]);
        }
        const int idx = row * DDIM + seg * 64 + j * 8;
        *(uint4*)(gCH + idx) = make_uint4(pk(h[0], h[1]), pk(h[2], h[3]), pk(h[4], h[5]), pk(h[6], h[7]));
        *(uint4*)(gCM + idx) = make_uint4(pk(m[0], m[1]), pk(m[2], m[3]), pk(m[4], m[5]), pk(m[6], m[7]));
        *(uint4*)(gCL + idx) = make_uint4(pk(l[0], l[1]), pk(l[2], l[3]), pk(l[4], l[5]), pk(l[6], l[7]));
    }
    acc += __shfl_xor_sync(0xffffffffu, acc, 1);
    acc += __shfl_xor_sync(0xffffffffu, acc, 2);
    if (seg == 0) {
        int mk = gmask[row];
        gCISM[row] = mk ? rsqrtf(fmaxf(acc, 1e-24f)) : 0.f;
        gNEGM[row] = mk ? 0.f : -1e9f;
    }
}

// cp.async one k-quarter (128B/row) of a precomputed split into pitched smem
__device__ __forceinline__ void copy_cq(uint32_t dstbase, const unsigned short* gsrc,
                                        int row, int seg, int kq) {
    uint32_t dst = dstbase + (uint32_t)(row * KQP + seg * 32);
    uint64_t src = __cvta_generic_to_global(gsrc + row * DDIM + kq * 64 + seg * 16);
    CPA16(dst, src);
    CPA16(dst + 16, src + 16);
}

__global__ void __launch_bounds__(NTHREADS, 3)
centroid_main(const float* __restrict__ gq,
              float* __restrict__ gctx,
              float* __restrict__ gw,
              float* __restrict__ ghard)
{
    extern __shared__ char sm[];
    const uint32_t smb = smem_u32(sm);
    const int t = threadIdx.x;
    const int wid = t >> 5, lane = t & 31;
    const int mbase = blockIdx.x * MTILE;

    float* qssf = (float*)(sm + QSS_O);
    float* cism = (float*)(sm + CISM_O);
    float* negm = (float*)(sm + NEGM_O);

    const int g = wid >> 2;
    const int mrow = ((wid >> 1) & 1) * 32;
    const int ncol = (wid & 1) * 32;
    const int row4 = t >> 2, seg4 = t & 3;

    if (t < 64) {
        cism[t] = gCISM[t];
        negm[t] = gNEGM[t];
    }

    float qacc = 0.f;
    float acc[8][4];
    #pragma unroll
    for (int i = 0; i < 8; ++i)
        #pragma unroll
        for (int j = 0; j < 4; ++j) acc[i][j] = 0.f;

    const uint32_t lrow = (uint32_t)(lane & 15);
    const uint32_t lk = (uint32_t)((lane >> 4) * 16);

    // ================= GEMM1 over four K-quarters =================
    #pragma unroll 1
    for (int kq = 0; kq < 4; ++kq) {
        copy_cq(smb + CH_O, gCH, row4, seg4, kq);
        copy_cq(smb + CM_O, gCM, row4, seg4, kq);
        copy_cq(smb + CL_O, gCL, row4, seg4, kq);
        CPA_COMMIT();
        // convert Q k-quarter [64][64] (16 elems/thread)
        {
            const float4* src = (const float4*)(gq + (size_t)(mbase + row4) * DDIM + kq * 64 + seg4 * 16);
            uint32_t base = (uint32_t)(row4 * KQP + seg4 * 32);
            conv8(src,     sm + QH_O, sm + QM_O, sm + QL_O, base,      qacc);
            conv8(src + 2, sm + QH_O, sm + QM_O, sm + QL_O, base + 16, qacc);
        }
        if (kq == 3) {
            qacc += __shfl_xor_sync(0xffffffffu, qacc, 1);
            qacc += __shfl_xor_sync(0xffffffffu, qacc, 2);
            if (seg4 == 0) qssf[row4] = qacc;
        }
        CPA_WAIT0();
        __syncthreads();
        // 3 split passes for this group, ks = 4
        {
            const uint32_t qofs[6] = {QH_O, QH_O, QM_O, QH_O, QL_O, QM_O};
            const uint32_t cofs[6] = {CH_O, CM_O, CH_O, CL_O, CH_O, CM_O};
            #pragma unroll 1
            for (int ps = 0; ps < 3; ++ps) {
                uint32_t ab = smb + qofs[g * 3 + ps] + (mrow + lrow) * KQP + lk;
                uint32_t bb = smb + cofs[g * 3 + ps] + (ncol + lrow) * KQP + lk;
                uint32_t bb2 = bb + 16 * KQP;
                #pragma unroll
                for (int ks = 0; ks < 4; ++ks) {
                    uint32_t a0, a1, a2, a3, a4, a5, a6, a7, e0, e1, e2, e3, f0, f1, f2, f3;
                    ldsm4(ab + ks * 32, a0, a1, a2, a3);
                    ldsm4(ab + 16 * KQP + ks * 32, a4, a5, a6, a7);
                    ldsm4(bb + ks * 32, e0, e1, e2, e3);
                    ldsm4(bb2 + ks * 32, f0, f1, f2, f3);
                    mma16816(acc[0], a0, a1, a2, a3, e0, e2);
                    mma16816(acc[1], a0, a1, a2, a3, e1, e3);
                    mma16816(acc[2], a0, a1, a2, a3, f0, f2);
                    mma16816(acc[3], a0, a1, a2, a3, f1, f3);
                    mma16816(acc[4], a4, a5, a6, a7, e0, e2);
                    mma16816(acc[5], a4, a5, a6, a7, e1, e3);
                    mma16816(acc[6], a4, a5, a6, a7, f0, f2);
                    mma16816(acc[7], a4, a5, a6, a7, f1, f3);
                }
            }
        }
        __syncthreads();
    }

    // ---- store partial sims ----
    {
        char* sbase = sm + (g ? S1_O : S0_O);
        const int r0 = mrow + (lane >> 2);
        const int cb = ncol + (lane & 3) * 2;
        #pragma unroll
        for (int mf = 0; mf < 2; ++mf)
            #pragma unroll
            for (int nf = 0; nf < 4; ++nf) {
                float* a = acc[mf * 4 + nf];
                *(float2*)(sbase + (r0 + mf * 16) * SP + (cb + nf * 8) * 4) = make_float2(a[0], a[1]);
                *(float2*)(sbase + (r0 + mf * 16 + 8) * SP + (cb + nf * 8) * 4) = make_float2(a[2], a[3]);
            }
    }
    __syncthreads();

    // ================= softmax + argmax: 4 threads per row =================
    {
        const int m = t >> 2, part = t & 3;
        const float qr = rsqrtf(fmaxf(qssf[m], 1e-24f));
        const float4* s0 = (const float4*)(sm + S0_O + m * SP) + part * 4;
        const float4* s1 = (const float4*)(sm + S1_O + m * SP) + part * 4;
        float s[16];
        float mx = -INFINITY;
        int mi = PDIM;
        #pragma unroll
        for (int gg = 0; gg < 4; ++gg) {
            float4 v = s0[gg], u = s1[gg];
            float vv[4] = {v.x + u.x, v.y + u.y, v.z + u.z, v.w + u.w};
            #pragma unroll
            for (int i = 0; i < 4; ++i) {
                int p = part * 16 + gg * 4 + i;
                float val = fmaf(vv[i] * qr, cism[p], negm[p]);
                s[gg * 4 + i] = val;
                if (val > mx) { mx = val; mi = p; }     // strict >: first index wins
            }
        }
        #pragma unroll
        for (int off = 1; off < 4; off <<= 1) {
            float omx = __shfl_xor_sync(0xffffffffu, mx, off);
            int   omi = __shfl_xor_sync(0xffffffffu, mi, off);
            if (omx > mx || (omx == mx && omi < mi)) { mx = omx; mi = omi; }
        }
        float ssum = 0.f;
        #pragma unroll
        for (int i = 0; i < 16; ++i) {
            float e = expf(s[i] - mx);
            s[i] = e;
            ssum += e;
        }
        #pragma unroll
        for (int off = 1; off < 4; off <<= 1)
            ssum += __shfl_xor_sync(0xffffffffu, ssum, off);
        const float inv = 1.0f / ssum;

        // W lives above sims region: no aliasing hazard, write directly
        float4* gwp = (float4*)(gw + (size_t)(mbase + m) * PDIM + part * 16);
        char* wh = sm + WH_O + m * WP + part * 32;
        char* wl = sm + WL_O + m * WP + part * 32;
        #pragma unroll
        for (int gg = 0; gg < 4; ++gg) {
            float w0 = s[4 * gg + 0] * inv, w1 = s[4 * gg + 1] * inv;
            float w2 = s[4 * gg + 2] * inv, w3 = s[4 * gg + 3] * inv;
            gwp[gg] = make_float4(w0, w1, w2, w3);
            unsigned short h0, l0, h1, l1, h2, l2, h3, l3;
            split2(w0, h0, l0); split2(w1, h1, l1);
            split2(w2, h2, l2); split2(w3, h3, l3);
            *(uint2*)(wh + gg * 8) = make_uint2(pk(h0, h1), pk(h2, h3));
            *(uint2*)(wl + gg * 8) = make_uint2(pk(l0, l1), pk(l2, l3));
        }
        if (part == 0) ghard[mbase + m] = (float)mi;
    }
    __syncthreads();

    // ================= GEMM2: 4 d-quarter rounds =================
    {
        const int mrow2 = (wid & 1) * 32;
        const int dt = (wid >> 1) * 16;              // 4 d-tiles of 16 cover the quarter
        const uint32_t btrow = (uint32_t)((lane >> 4) * 8 + (lane & 7));
        const uint32_t btcol = (uint32_t)(((lane >> 3) & 1) * 16);
        const uint32_t wofs[3] = {WH_O, WH_O, WL_O};
        const uint32_t cofs2[3] = {C2H_O, C2M_O, C2H_O};   // C mid == split2-lo of C

        #pragma unroll 1
        for (int dq = 0; dq < 4; ++dq) {
            copy_cq(smb + C2H_O, gCH, row4, seg4, dq);
            copy_cq(smb + C2M_O, gCM, row4, seg4, dq);
            CPA_COMMIT();
            CPA_WAIT0();
            __syncthreads();

            float dd[4][4];
            #pragma unroll
            for (int i = 0; i < 4; ++i)
                #pragma unroll
                for (int j = 0; j < 4; ++j) dd[i][j] = 0.f;

            #pragma unroll 1
            for (int ps = 0; ps < 3; ++ps) {
                uint32_t ab = smb + wofs[ps] + (mrow2 + lrow) * WP + lk;
                uint32_t bb = smb + cofs2[ps] + btrow * KQP + dt * 2 + btcol;
                #pragma unroll
                for (int ks = 0; ks < 4; ++ks) {
                    uint32_t a0, a1, a2, a3, a4, a5, a6, a7, r0, r1, r2, r3;
                    ldsm4(ab + ks * 32, a0, a1, a2, a3);
                    ldsm4(ab + 16 * WP + ks * 32, a4, a5, a6, a7);
                    ldsm4t(bb + ks * 16 * KQP, r0, r1, r2, r3);
                    mma16816(dd[0], a0, a1, a2, a3, r0, r2);
                    mma16816(dd[1], a0, a1, a2, a3, r1, r3);
                    mma16816(dd[2], a4, a5, a6, a7, r0, r2);
                    mma16816(dd[3], a4, a5, a6, a7, r1, r3);
                }
            }
            // store this d-quarter slice
            const int r0l = lane >> 2;
            const int cb = dq * 64 + dt + (lane & 3) * 2;
            #pragma unroll
            for (int mf = 0; mf < 2; ++mf) {
                float* gr0 = gctx + (size_t)(mbase + mrow2 + mf * 16 + r0l) * DDIM;
                float* gr1 = gr0 + 8 * DDIM;
                #pragma unroll
                for (int nf = 0; nf < 2; ++nf) {
                    float* a = dd[mf * 2 + nf];
                    *(float2*)(gr0 + cb + nf * 8) = make_float2(a[0], a[1]);
                    *(float2*)(gr1 + cb + nf * 8) = make_float2(a[2], a[3]);
                }
            }
            __syncthreads();
        }
    }
}

extern "C" void kernel_launch(void* const* d_in, const int* in_sizes, int n_in,
                              void* d_out, int out_size)
{
    const float* q = (const float*)d_in[0];
    const float* c = (const float*)d_in[1];
    const int*   mask = (const int*)d_in[2];

    const int Pn = in_sizes[2];              // 64
    const int Dn = in_sizes[1] / Pn;         // 256
    const int B  = in_sizes[0] / Dn;         // 131072

    float* out  = (float*)d_out;
    float* ctx  = out;                           // [B, D]
    float* w    = out + (size_t)B * Dn;          // [B, P]
    float* hard = w + (size_t)B * Pn;            // [B]

    centroid_prep<<<1, 256>>>(c, mask);
    cudaFuncSetAttribute(centroid_main,
                         cudaFuncAttributeMaxDynamicSharedMemorySize, SMEM_BYTES);
    centroid_main<<<B / MTILE, NTHREADS, SMEM_BYTES>>>(q, ctx, w, hard);
}